// round 7
// baseline (speedup 1.0000x reference)
#include <cuda_runtime.h>
#include <cstdint>

// MyConvNet fused kernel, one CTA per image, 576 threads (18 warps).
//  conv1 1->64 3x3 -> 26x26 ; maxpool 3/2 -> 12x12 ; relu
//  conv2 64->64 3x3 -> 10x10 ; maxpool 3/2 -> 4x4  ; relu
//  conv3 64->10 4x4 -> 1x1   ; out [B,10]
// h1 stored as duplicated (v,v) f32 pairs -> conv2 reads activations with one
// broadcast LDS.64 (no pack MOVs). Phase 2 uses a 3x3 position tile with
// row-streamed activation loads (5-stage pipeline per ic) to hide LDS latency.

typedef unsigned long long ull;

__device__ __forceinline__ ull pack2(float lo, float hi) {
    ull v;
    asm("mov.b64 %0, {%1, %2};" : "=l"(v) : "f"(lo), "f"(hi));
    return v;
}
__device__ __forceinline__ void unpack2(ull v, float& lo, float& hi) {
    asm("mov.b64 {%0, %1}, %2;" : "=f"(lo), "=f"(hi) : "l"(v));
}
__device__ __forceinline__ void fma2(ull& d, ull a, ull b) {
    asm("fma.rn.f32x2 %0, %1, %2, %0;" : "+l"(d) : "l"(a), "l"(b));
}
__device__ __forceinline__ void add2(ull& d, ull a) {
    asm("add.rn.f32x2 %0, %0, %1;" : "+l"(d) : "l"(a));
}

// ---- shared memory layout (float offsets) ----
// x_s   :     0 ..   784
// w1_s  :   784 ..  1360   (64*9)
// b1_s  :  1360 ..  1424
// b2_s  :  1424 ..  1488
// h1d   :  1488 .. 18640   (64 ch * 134-ull stride, duplicated pairs;
//                           pos = row*12+col, rows 0..10)
// w2t   : 18640 .. 57808   (576 * 68; w2 transposed [k][oc], row pad 68)
//   aliases inside w2t region (weights dead after phase-2 main loop):
//     scratch : w2t + 0      (phase-2 partials)
//     c2_s    : w2t + 24000  (5184 floats)
//     h2_s    : w2t + 30000  (1024 floats)
#define SMEM_FLOATS 57808
#define SMEM_BYTES  (SMEM_FLOATS * 4)
#define NT 576
#define H1_STRIDE 134

__global__ void __launch_bounds__(NT, 1)
convnet_kernel(const float* __restrict__ x,
               const float* __restrict__ w1, const float* __restrict__ b1,
               const float* __restrict__ w2, const float* __restrict__ b2,
               const float* __restrict__ w3, const float* __restrict__ b3,
               float* __restrict__ out)
{
    extern __shared__ float sm[];
    float* x_s  = sm;
    float* w1_s = sm + 784;
    float* b1_s = sm + 1360;
    float* b2_s = sm + 1424;
    ull*   h1d  = reinterpret_cast<ull*>(sm + 1488);   // 16B-aligned base
    float* w2t  = sm + 18640;
    float* c2_s = w2t + 24000;
    float* h2_s = w2t + 30000;

    const int tid  = threadIdx.x;
    const int img  = blockIdx.x;
    const int wid  = tid >> 5;
    const int lane = tid & 31;

    // ---------------- Phase 0: loads ----------------
    {
        const float* xg = x + img * 784;
        for (int i = tid; i < 784; i += NT) x_s[i] = xg[i];
        if (tid < 576) w1_s[tid] = w1[tid];
        if (tid < 64) { b1_s[tid] = b1[tid]; b2_s[tid] = b2[tid]; }

        // w2 transpose: w2t[k*68 + oc] = w2[oc*576 + k], vectorized LDG.128
        if (wid < 16) {
            const int ol = lane >> 3;   // 0..3
            const int kl = lane & 7;    // 0..7
            const int oc = wid * 4 + ol;
            const float4* src = reinterpret_cast<const float4*>(w2 + oc * 576);
            #pragma unroll 3
            for (int j = 0; j < 18; j++) {
                const float4 v = __ldg(src + kl + 8 * j);
                const int k = 4 * (kl + 8 * j);
                w2t[(k + 0) * 68 + oc] = v.x;
                w2t[(k + 1) * 68 + oc] = v.y;
                w2t[(k + 2) * 68 + oc] = v.z;
                w2t[(k + 3) * 68 + oc] = v.w;
            }
        }
    }
    __syncthreads();

    // ------- Phase 1: conv1 + maxpool(3,2) + relu -> h1d (duplicated) -------
    {
        const int ch = tid & 63;
        const int g0 = tid >> 6;   // 0..8
        const float bc = b1_s[ch];
        ull wp[9];
        #pragma unroll
        for (int j = 0; j < 9; j++) {
            const float w = w1_s[ch * 9 + j];
            wp[j] = pack2(w, w);
        }

        #pragma unroll 1
        for (int it = 0; it < 8; it++) {
            const int pr = g0 + 9 * it;        // 0..71
            if (pr < 66) {
                const int py  = pr / 6;            // 0..10
                const int px0 = (pr - py * 6) * 2; // 0,2,4,6,8,10

                const float* xp = x_s + (2 * py) * 28 + 2 * px0;
                ull pa[5][5];
                #pragma unroll
                for (int r = 0; r < 5; r++) {
                    float row[7];
                    #pragma unroll
                    for (int c = 0; c < 7; c++) row[c] = xp[r * 28 + c];
                    #pragma unroll
                    for (int c = 0; c < 5; c++) pa[r][c] = pack2(row[c], row[c + 2]);
                }

                float m0 = -3.0e38f, m1 = -3.0e38f;
                #pragma unroll
                for (int dy = 0; dy < 3; dy++)
                    #pragma unroll
                    for (int dx = 0; dx < 3; dx++) {
                        ull s2 = 0ull;
                        #pragma unroll
                        for (int r = 0; r < 3; r++)
                            #pragma unroll
                            for (int cc = 0; cc < 3; cc++)
                                fma2(s2, wp[r * 3 + cc], pa[dy + r][dx + cc]);
                        float s0, s1;
                        unpack2(s2, s0, s1);
                        m0 = fmaxf(m0, s0);
                        m1 = fmaxf(m1, s1);
                    }
                const float v0 = fmaxf(m0 + bc, 0.f);
                const float v1 = fmaxf(m1 + bc, 0.f);
                *reinterpret_cast<float4*>(h1d + ch * H1_STRIDE + py * 12 + px0) =
                    make_float4(v0, v0, v1, v1);
            }
        }
    }
    __syncthreads();

    // ------- Phase 2: conv2 at 9x9 positions, 4-way ic split -------
    // thread tile: 4 oc x (3x3 position block); 16 ic per group.
    // 16 ocb * 9 blocks * 4 groups = 576 threads.
    const int group = tid / 144;          // 0..3
    const int wi    = tid - group * 144;  // 0..143
    const int ocb   = wi & 15;            // 0..15 -> oc0 = 4*ocb
    const int bb    = wi >> 4;            // 0..8 position block
    const int by    = bb / 3;             // 0..2
    const int bx    = bb - 3 * by;        // 0..2
    const int oc0   = ocb * 4;

    ull acc[3][3][2];
    #pragma unroll
    for (int jy = 0; jy < 3; jy++)
        #pragma unroll
        for (int jx = 0; jx < 3; jx++) { acc[jy][jx][0] = 0ull; acc[jy][jx][1] = 0ull; }

    {
        const int ic0 = group * 16;
        #pragma unroll 1
        for (int ic = ic0; ic < ic0 + 16; ic++) {
            const ull*   hbase = h1d + ic * H1_STRIDE + (3 * by) * 12 + 3 * bx;
            const float* wk    = w2t + (ic * 9) * 68 + oc0;

            // all 9 weight vectors for this ic (LDS.128 each)
            ulonglong2 wv[3][3];
            #pragma unroll
            for (int r = 0; r < 3; r++)
                #pragma unroll
                for (int cn = 0; cn < 3; cn++)
                    wv[r][cn] = *reinterpret_cast<const ulonglong2*>(
                        wk + (r * 3 + cn) * 68);

            // stream activation rows t = 0..4; row t feeds out-rows jy=t-r
            #pragma unroll
            for (int t = 0; t < 5; t++) {
                ull ar[5];
                #pragma unroll
                for (int c = 0; c < 5; c++) ar[c] = hbase[t * 12 + c];
                const int jy_lo = (t > 2) ? (t - 2) : 0;
                const int jy_hi = (t < 2) ? t : 2;
                #pragma unroll
                for (int jy = 0; jy < 3; jy++) {
                    if (jy >= jy_lo && jy <= jy_hi) {
                        const int r = t - jy;
                        #pragma unroll
                        for (int cn = 0; cn < 3; cn++)
                            #pragma unroll
                            for (int jx = 0; jx < 3; jx++) {
                                fma2(acc[jy][jx][0], wv[r][cn].x, ar[jx + cn]);
                                fma2(acc[jy][jx][1], wv[r][cn].y, ar[jx + cn]);
                            }
                    }
                }
            }
        }
    }
    __syncthreads();  // all groups done reading w2t -> safe to reuse region

    // partials -> scratch (aliases w2t region), then packed reduction
    {
        ull* scratch = reinterpret_cast<ull*>(w2t);
        #pragma unroll
        for (int jy = 0; jy < 3; jy++)
            #pragma unroll
            for (int jx = 0; jx < 3; jx++) {
                const int pos = (3 * by + jy) * 9 + (3 * bx + jx);
                #pragma unroll
                for (int q = 0; q < 2; q++) {
                    const int p = ocb * 2 + q;  // oc pair index 0..31
                    scratch[(p * 81 + pos) * 4 + group + p] = acc[jy][jx][q];
                }
            }
        __syncthreads();
        for (int u = tid; u < 2592; u += NT) {
            const int p   = u / 81;
            const int pos = u - p * 81;
            const ull* s  = scratch + u * 4 + p;
            ull v = s[0];
            add2(v, s[1]);
            add2(v, s[2]);
            add2(v, s[3]);
            float lo, hi;
            unpack2(v, lo, hi);
            const int oc = 2 * p;
            c2_s[oc * 81 + pos]      = lo + b2_s[oc];
            c2_s[oc * 81 + 81 + pos] = hi + b2_s[oc + 1];
        }
    }
    __syncthreads();

    // ------- Phase 3: maxpool2(3,2) + relu -> h2 [64][16] -------
    for (int i = tid; i < 1024; i += NT) {
        const int oc = i >> 4;
        const int p  = i & 15;
        const int j  = p >> 2, ii = p & 3;
        const float* base = c2_s + oc * 81 + (2 * j) * 9 + 2 * ii;
        float m = base[0];
        #pragma unroll
        for (int dy = 0; dy < 3; dy++)
            #pragma unroll
            for (int dx = 0; dx < 3; dx++) m = fmaxf(m, base[dy * 9 + dx]);
        h2_s[oc * 16 + p] = fmaxf(m, 0.f);
    }
    __syncthreads();

    // ------- Phase 4: conv3 (10 dots over 1024), float4 both sides -------
    if (wid < 10) {
        const float4* wp = reinterpret_cast<const float4*>(w3 + (wid << 10));
        const float4* hp = reinterpret_cast<const float4*>(h2_s);
        float sres = 0.f;
        #pragma unroll
        for (int m = 0; m < 8; m++) {
            const float4 wv = __ldg(wp + lane + 32 * m);
            const float4 hv = hp[lane + 32 * m];
            sres = fmaf(wv.x, hv.x, sres);
            sres = fmaf(wv.y, hv.y, sres);
            sres = fmaf(wv.z, hv.z, sres);
            sres = fmaf(wv.w, hv.w, sres);
        }
        #pragma unroll
        for (int off = 16; off > 0; off >>= 1)
            sres += __shfl_down_sync(0xffffffffu, sres, off);
        if (lane == 0) out[img * 10 + wid] = sres + b3[wid];
    }
}

extern "C" void kernel_launch(void* const* d_in, const int* in_sizes, int n_in,
                              void* d_out, int out_size)
{
    const float* x  = (const float*)d_in[0];
    const float* w1 = (const float*)d_in[1];
    const float* b1 = (const float*)d_in[2];
    const float* w2 = (const float*)d_in[3];
    const float* b2 = (const float*)d_in[4];
    const float* w3 = (const float*)d_in[5];
    const float* b3 = (const float*)d_in[6];
    float* out = (float*)d_out;

    const int B = in_sizes[0] / 784;

    cudaFuncSetAttribute(convnet_kernel,
                         cudaFuncAttributeMaxDynamicSharedMemorySize, SMEM_BYTES);

    convnet_kernel<<<B, NT, SMEM_BYTES>>>(x, w1, b1, w2, b2, w3, b3, out);
}

// round 11
// speedup vs baseline: 2.7857x; 2.7857x over previous
#include <cuda_runtime.h>
#include <cuda_bf16.h>
#include <cstdint>

// MyConvNet fused, one CTA per image, 256 threads (8 warps), 2 CTAs/SM.
//  conv1+pool1+relu : FFMA packed f32x2, writes Ht (bf16 hi/lo, pos-major)
//  conv2            : mma.sync m16n8k16 bf16, 3-pass (Ah*Bh + Al*Bh + Ah*Bl),
//                     9 shift-GEMMs, fp32 accumulators in registers
//  pool2+relu, conv3: FFMA
// B tiles (image-invariant) pre-packed in fragment-friendly layout by prep_kernel.

typedef unsigned long long ull;

__device__ __forceinline__ ull pack2(float lo, float hi) {
    ull v; asm("mov.b64 %0, {%1, %2};" : "=l"(v) : "f"(lo), "f"(hi)); return v;
}
__device__ __forceinline__ void unpack2(ull v, float& lo, float& hi) {
    asm("mov.b64 {%0, %1}, %2;" : "=f"(lo), "=f"(hi) : "l"(v));
}
__device__ __forceinline__ void fma2(ull& d, ull a, ull b) {
    asm("fma.rn.f32x2 %0, %1, %2, %0;" : "+l"(d) : "l"(a), "l"(b));
}

// D(16x8,f32) += A(16x16,bf16,row) * B(16x8,bf16,col)
__device__ __forceinline__ void mma_bf16(float* d, const uint32_t* a,
                                         uint32_t b0, uint32_t b1) {
    asm volatile(
        "mma.sync.aligned.m16n8k16.row.col.f32.bf16.bf16.f32 "
        "{%0,%1,%2,%3}, {%4,%5,%6,%7}, {%8,%9}, {%0,%1,%2,%3};"
        : "+f"(d[0]), "+f"(d[1]), "+f"(d[2]), "+f"(d[3])
        : "r"(a[0]), "r"(a[1]), "r"(a[2]), "r"(a[3]), "r"(b0), "r"(b1));
}

// ---- smem layout (float offsets) ----
#define X_OFF    0
#define W1_OFF   784
#define B1_OFF   1360
#define B2_OFF   1424
#define HT_HI    1488            // 160 rows x 36 words (bf16x2) = 5760
#define HT_LO    7248            // 5760
#define BS_OFF   13008           // 2 buffers x 4608 words
#define C2_OFF   1488            // alias over Ht after all MMAs: [128 m][66]
#define H2_OFF   13008           // alias over BS after all MMAs: 1024
#define SMEM_FLOATS 22224
#define SMEM_BYTES  (SMEM_FLOATS * 4)
#define NT 256
#define HTW 36                   // words per Ht row (72 bf16, 64 used)

// prebuilt B tiles: [s][pr(hi,lo)][64 oc][36 words] ; word = bf16x2 (ic even, odd)
__device__ __align__(16) uint32_t g_B[9 * 2 * 64 * 36];

__global__ void prep_kernel(const float* __restrict__ w2) {
    const int s = blockIdx.x;                    // shift 0..8
    for (int i = threadIdx.x; i < 2048; i += blockDim.x) {
        const int oc = i >> 5, w = i & 31;       // word w = ic pair (2w, 2w+1)
        const float v0 = w2[oc * 576 + (2 * w) * 9 + s];
        const float v1 = w2[oc * 576 + (2 * w + 1) * 9 + s];
        const __nv_bfloat162 h = __floats2bfloat162_rn(v0, v1);
        const float r0 = v0 - __bfloat162float(h.x);
        const float r1 = v1 - __bfloat162float(h.y);
        const __nv_bfloat162 l = __floats2bfloat162_rn(r0, r1);
        g_B[(s * 2 + 0) * 2304 + oc * HTW + w] = *reinterpret_cast<const uint32_t*>(&h);
        g_B[(s * 2 + 1) * 2304 + oc * HTW + w] = *reinterpret_cast<const uint32_t*>(&l);
    }
}

__global__ void __launch_bounds__(NT, 2)
convnet_kernel(const float* __restrict__ x,
               const float* __restrict__ w1, const float* __restrict__ b1,
               const float* __restrict__ b2,
               const float* __restrict__ w3, const float* __restrict__ b3,
               float* __restrict__ out)
{
    extern __shared__ float sm[];
    const int tid  = threadIdx.x;
    const int img  = blockIdx.x;
    const int wid  = tid >> 5;
    const int lane = tid & 31;
    const int g    = lane >> 2;   // fragment group row
    const int t    = lane & 3;    // fragment thread-in-group

    // ---------------- Phase 0: loads + B(s=0) copy ----------------
    {
        const float* xg = x + img * 784;
        for (int i = tid; i < 784; i += NT) sm[X_OFF + i] = xg[i];
        for (int i = tid; i < 576; i += NT) sm[W1_OFF + i] = w1[i];
        if (tid < 64) { sm[B1_OFF + tid] = b1[tid]; sm[B2_OFF + tid] = b2[tid]; }
        const uint4* src = reinterpret_cast<const uint4*>(g_B);
        uint4* dst = reinterpret_cast<uint4*>(sm + BS_OFF);
        for (int i = tid; i < 1152; i += NT) dst[i] = __ldg(src + i);
    }
    __syncthreads();

    // ------- Phase 1: conv1 + maxpool(3,2) + relu -> Ht bf16 hi/lo -------
    {
        const int ch = tid & 63;
        const int g0 = tid >> 6;   // 0..3
        const float bc = sm[B1_OFF + ch];
        ull wp[9];
        #pragma unroll
        for (int j = 0; j < 9; j++) {
            const float w = sm[W1_OFF + ch * 9 + j];
            wp[j] = pack2(w, w);
        }
        __nv_bfloat16* HHb = reinterpret_cast<__nv_bfloat16*>(sm + HT_HI);
        __nv_bfloat16* HLb = reinterpret_cast<__nv_bfloat16*>(sm + HT_LO);

        #pragma unroll 1
        for (int it = 0; it < 17; it++) {
            const int pr = g0 + 4 * it;        // 0..65
            if (pr < 66) {
                const int py  = pr / 6;            // 0..10
                const int px0 = (pr - py * 6) * 2; // 0..10 even
                const float* xp = sm + X_OFF + (2 * py) * 28 + 2 * px0;
                ull pa[5][5];
                #pragma unroll
                for (int r = 0; r < 5; r++) {
                    float row[7];
                    #pragma unroll
                    for (int c = 0; c < 7; c++) row[c] = xp[r * 28 + c];
                    #pragma unroll
                    for (int c = 0; c < 5; c++) pa[r][c] = pack2(row[c], row[c + 2]);
                }
                float m0 = -3.0e38f, m1 = -3.0e38f;
                #pragma unroll
                for (int dy = 0; dy < 3; dy++)
                    #pragma unroll
                    for (int dx = 0; dx < 3; dx++) {
                        ull s2 = 0ull;
                        #pragma unroll
                        for (int r = 0; r < 3; r++)
                            #pragma unroll
                            for (int cc = 0; cc < 3; cc++)
                                fma2(s2, wp[r * 3 + cc], pa[dy + r][dx + cc]);
                        float s0, s1;
                        unpack2(s2, s0, s1);
                        m0 = fmaxf(m0, s0);
                        m1 = fmaxf(m1, s1);
                    }
                const float v0 = fmaxf(m0 + bc, 0.f);
                const float v1 = fmaxf(m1 + bc, 0.f);
                const int pos = py * 12 + px0;
                const __nv_bfloat16 h0 = __float2bfloat16(v0);
                const __nv_bfloat16 h1 = __float2bfloat16(v1);
                HHb[pos * 72 + ch]       = h0;
                HHb[(pos + 1) * 72 + ch] = h1;
                HLb[pos * 72 + ch]       = __float2bfloat16(v0 - __bfloat162float(h0));
                HLb[(pos + 1) * 72 + ch] = __float2bfloat16(v1 - __bfloat162float(h1));
            }
        }
    }
    __syncthreads();

    // ------- Phase 2: 9 shift-GEMMs on mma.sync bf16 (3-pass split) -------
    float d[8][4];
    #pragma unroll
    for (int nt = 0; nt < 8; nt++)
        #pragma unroll
        for (int q = 0; q < 4; q++) d[nt][q] = 0.f;

    {
        const uint32_t* HH = reinterpret_cast<const uint32_t*>(sm + HT_HI);
        const uint32_t* HL = reinterpret_cast<const uint32_t*>(sm + HT_LO);

        #pragma unroll 1
        for (int s = 0; s < 9; s++) {
            // prefetch next shift's B into the other buffer (visible after bottom sync)
            if (s < 8) {
                const uint4* src = reinterpret_cast<const uint4*>(g_B) + (s + 1) * 1152;
                uint4* dst = reinterpret_cast<uint4*>(sm + BS_OFF) + ((s + 1) & 1) * 1152;
                for (int i = tid; i < 1152; i += NT) dst[i] = __ldg(src + i);
            }

            const int off = 12 * (s / 3) + (s % 3);
            const int rowA = 16 * wid + g + off;
            const uint32_t* pa = HH + rowA * HTW + t;   // hi
            const uint32_t* pl = HL + rowA * HTW + t;   // lo
            const uint32_t* BB = reinterpret_cast<const uint32_t*>(sm + BS_OFF)
                               + (s & 1) * 4608;

            #pragma unroll
            for (int ks = 0; ks < 4; ks++) {
                uint32_t ah[4], al[4];
                ah[0] = pa[ks * 8];            ah[2] = pa[ks * 8 + 4];
                ah[1] = pa[ks * 8 + 8 * HTW];  ah[3] = pa[ks * 8 + 8 * HTW + 4];
                al[0] = pl[ks * 8];            al[2] = pl[ks * 8 + 4];
                al[1] = pl[ks * 8 + 8 * HTW];  al[3] = pl[ks * 8 + 8 * HTW + 4];
                #pragma unroll
                for (int nt = 0; nt < 8; nt++) {
                    const uint32_t* pb = BB + (nt * 8 + g) * HTW + ks * 8 + t;
                    const uint32_t bh0 = pb[0],        bh1 = pb[4];
                    const uint32_t bl0 = pb[2304],     bl1 = pb[2304 + 4];
                    mma_bf16(d[nt], ah, bh0, bh1);
                    mma_bf16(d[nt], al, bh0, bh1);
                    mma_bf16(d[nt], ah, bl0, bl1);
                }
            }
            __syncthreads();
        }
    }

    // ------- D writeout: c2[m][66] = D + b2 (aliases Ht region) -------
    float* c2 = sm + C2_OFF;
    {
        const int row0 = 16 * wid + g;
        #pragma unroll
        for (int nt = 0; nt < 8; nt++) {
            const int oc = nt * 8 + 2 * t;
            const float bb0 = sm[B2_OFF + oc];
            const float bb1 = sm[B2_OFF + oc + 1];
            *reinterpret_cast<float2*>(c2 + row0 * 66 + oc) =
                make_float2(d[nt][0] + bb0, d[nt][1] + bb1);
            *reinterpret_cast<float2*>(c2 + (row0 + 8) * 66 + oc) =
                make_float2(d[nt][2] + bb0, d[nt][3] + bb1);
        }
    }
    __syncthreads();

    // ------- Phase 3: maxpool2(3,2) + relu -> h2 [64][16] (aliases BS) -------
    float* h2 = sm + H2_OFF;
    for (int i = tid; i < 1024; i += NT) {
        const int oc = i >> 4;
        const int p  = i & 15;
        const int j  = p >> 2, ii = p & 3;
        const int m0 = (2 * j) * 12 + 2 * ii;
        float m = -3.0e38f;
        #pragma unroll
        for (int dy = 0; dy < 3; dy++)
            #pragma unroll
            for (int dx = 0; dx < 3; dx++)
                m = fmaxf(m, c2[(m0 + dy * 12 + dx) * 66 + oc]);
        h2[oc * 16 + p] = fmaxf(m, 0.f);
    }
    __syncthreads();

    // ------- Phase 4: conv3 (10 dots over 1024) -------
    for (int o = wid; o < 10; o += 8) {
        const float4* wp = reinterpret_cast<const float4*>(w3 + (o << 10));
        const float4* hp = reinterpret_cast<const float4*>(h2);
        float sres = 0.f;
        #pragma unroll
        for (int m = 0; m < 8; m++) {
            const float4 wv = __ldg(wp + lane + 32 * m);
            const float4 hv = hp[lane + 32 * m];
            sres = fmaf(wv.x, hv.x, sres);
            sres = fmaf(wv.y, hv.y, sres);
            sres = fmaf(wv.z, hv.z, sres);
            sres = fmaf(wv.w, hv.w, sres);
        }
        #pragma unroll
        for (int off = 16; off > 0; off >>= 1)
            sres += __shfl_down_sync(0xffffffffu, sres, off);
        if (lane == 0) out[img * 10 + o] = sres + b3[o];
    }
}

extern "C" void kernel_launch(void* const* d_in, const int* in_sizes, int n_in,
                              void* d_out, int out_size)
{
    const float* x  = (const float*)d_in[0];
    const float* w1 = (const float*)d_in[1];
    const float* b1 = (const float*)d_in[2];
    const float* w2 = (const float*)d_in[3];
    const float* b2 = (const float*)d_in[4];
    const float* w3 = (const float*)d_in[5];
    const float* b3 = (const float*)d_in[6];
    float* out = (float*)d_out;

    const int B = in_sizes[0] / 784;

    cudaFuncSetAttribute(convnet_kernel,
                         cudaFuncAttributeMaxDynamicSharedMemorySize, SMEM_BYTES);

    prep_kernel<<<9, 256>>>(w2);
    convnet_kernel<<<B, NT, SMEM_BYTES>>>(x, w1, b1, b2, w3, b3, out);
}